// round 3
// baseline (speedup 1.0000x reference)
#include <cuda_runtime.h>
#include <cuda_bf16.h>
#include <cstdint>

// UniformNeighborSampler: for each of BATCH rows, gather 128 neighbor ids,
// gather their probs from prob_matrix[id, :], take stable top-25 (desc value,
// asc index), emit the neighbor ids.
//
// One warp per batch row. Each lane holds 4 (key, neighbor) pairs.
// Key = (ordered_float_bits(w) << 32) | (0xFFFFFFFF - local_idx)  -- unique,
// max-key order == jax.lax.top_k order (descending value, ties -> lower idx).
//
// Output is written as FLOAT32 (harness __output__ dtype): ids < 2^24 are
// exactly representable.

#define N_NODES     20000
#define MAX_DEGREE  128
#define BATCH       4096
#define NUM_SAMPLES 25
#define WARPS_PER_BLOCK 8
#define THREADS (WARPS_PER_BLOCK * 32)

__device__ __forceinline__ unsigned int ordered_bits(float f) {
    unsigned int u = __float_as_uint(f);
    unsigned int mask = (u & 0x80000000u) ? 0xFFFFFFFFu : 0x80000000u;
    return u ^ mask;
}

__global__ __launch_bounds__(THREADS)
void uns_topk_kernel(const int* __restrict__ ids,
                     const int* __restrict__ adj_info,
                     const float* __restrict__ prob,
                     float* __restrict__ out)
{
    const int warp_id = (blockIdx.x * WARPS_PER_BLOCK) + (threadIdx.x >> 5);
    const int lane    = threadIdx.x & 31;
    if (warp_id >= BATCH) return;

    const int id = ids[warp_id];

    // coalesced: lane loads 4 consecutive neighbor ids
    const int4* adj4 = reinterpret_cast<const int4*>(adj_info + (long long)id * MAX_DEGREE);
    int4 nb = adj4[lane];

    const float* prow = prob + (long long)id * N_NODES;

    // 4 independent random gathers per lane (MLP=4 per lane, 128 per warp)
    float w0 = __ldg(&prow[nb.x]);
    float w1 = __ldg(&prow[nb.y]);
    float w2 = __ldg(&prow[nb.z]);
    float w3 = __ldg(&prow[nb.w]);

    const int base_idx = lane * 4;
    unsigned long long key[4];
    key[0] = ((unsigned long long)ordered_bits(w0) << 32) | (0xFFFFFFFFu - (base_idx + 0));
    key[1] = ((unsigned long long)ordered_bits(w1) << 32) | (0xFFFFFFFFu - (base_idx + 1));
    key[2] = ((unsigned long long)ordered_bits(w2) << 32) | (0xFFFFFFFFu - (base_idx + 2));
    key[3] = ((unsigned long long)ordered_bits(w3) << 32) | (0xFFFFFFFFu - (base_idx + 3));

    int nbv[4] = { nb.x, nb.y, nb.z, nb.w };

    float* orow = out + (long long)warp_id * NUM_SAMPLES;

    #pragma unroll 1
    for (int s = 0; s < NUM_SAMPLES; s++) {
        // local max over the 4 slots
        unsigned long long lk = key[0];
        int lj = 0;
        if (key[1] > lk) { lk = key[1]; lj = 1; }
        if (key[2] > lk) { lk = key[2]; lj = 2; }
        if (key[3] > lk) { lk = key[3]; lj = 3; }

        // warp-wide max (keys are unique)
        unsigned long long mk = lk;
        #pragma unroll
        for (int off = 16; off > 0; off >>= 1) {
            unsigned long long o = __shfl_xor_sync(0xFFFFFFFFu, mk, off);
            if (o > mk) mk = o;
        }

        if (lk == mk) {
            orow[s] = (float)nbv[lj];   // float32 output: ids exact < 2^24
            key[lj] = 0ull;             // remove from further consideration
        }
    }
}

extern "C" void kernel_launch(void* const* d_in, const int* in_sizes, int n_in,
                              void* d_out, int out_size)
{
    // Identify inputs by size (robust to metadata ordering). Element counts:
    //   ids: 4096, adj_info: 2,560,000, prob_matrix: 400,000,000
    // Also accept byte counts in case in_sizes are bytes.
    const int*   ids  = nullptr;
    const int*   adj  = nullptr;
    const float* prob = nullptr;

    const long long S_IDS  = (long long)BATCH;
    const long long S_ADJ  = (long long)N_NODES * MAX_DEGREE;
    const long long S_PROB = (long long)N_NODES * N_NODES;

    for (int i = 0; i < n_in; i++) {
        long long sz = (long long)(unsigned int)in_sizes[i];
        if (sz == S_IDS  || sz == S_IDS  * 4) ids  = (const int*)d_in[i];
        else if (sz == S_ADJ  || sz == S_ADJ  * 4) adj  = (const int*)d_in[i];
        else if (sz == S_PROB || sz == S_PROB * 4) prob = (const float*)d_in[i];
    }

    // Fallback: setup_inputs dict order (ids, adj_info, prob_matrix, num_samples)
    if (!ids || !adj || !prob) {
        ids  = (const int*)d_in[0];
        adj  = (const int*)d_in[1];
        prob = (const float*)d_in[2];
    }

    float* out = (float*)d_out;

    const int grid = (BATCH + WARPS_PER_BLOCK - 1) / WARPS_PER_BLOCK;  // 512
    uns_topk_kernel<<<grid, THREADS>>>(ids, adj, prob, out);
}

// round 8
// speedup vs baseline: 1.3163x; 1.3163x over previous
#include <cuda_runtime.h>
#include <cuda_bf16.h>
#include <cstdint>

// UniformNeighborSampler, rank-based selection.
//
// One 128-thread block per batch row; one neighbor element per thread.
// key = (ordered_bits(w) << 32) | (127 - tid)  -- unique per row; key-descending
// order == jax.lax.top_k order (descending w, ties -> lower index).
// Each thread counts keys greater than its own (rank); ranks form a
// permutation of 0..127, so threads with rank < 25 scatter their neighbor id
// (as float32, the harness output dtype) to out[row*25 + rank].
//
// No shuffles, no serial rounds: the rank loop is 128 broadcast LDS reads +
// 64-bit compares, fully pipelined; occupancy is block-count driven (4096
// blocks -> full 64 warps/SM).

#define N_NODES     20000
#define MAX_DEGREE  128
#define BATCH       4096
#define NUM_SAMPLES 25
#define THREADS     128

__device__ __forceinline__ unsigned int ordered_bits(float f) {
    unsigned int u = __float_as_uint(f);
    unsigned int mask = (u & 0x80000000u) ? 0xFFFFFFFFu : 0x80000000u;
    return u ^ mask;
}

__global__ __launch_bounds__(THREADS)
void uns_rank_kernel(const int* __restrict__ ids,
                     const int* __restrict__ adj_info,
                     const float* __restrict__ prob,
                     float* __restrict__ out)
{
    __shared__ unsigned long long skey[MAX_DEGREE];

    const int row = blockIdx.x;
    const int tid = threadIdx.x;

    const int id = __ldg(&ids[row]);                      // uniform broadcast

    const int nb = __ldg(&adj_info[(long long)id * MAX_DEGREE + tid]); // coalesced
    const float w = __ldg(&prob[(long long)id * N_NODES + nb]);        // random gather

    const unsigned long long mykey =
        ((unsigned long long)ordered_bits(w) << 32) | (unsigned int)(MAX_DEGREE - 1 - tid);

    skey[tid] = mykey;
    __syncthreads();

    // Count keys strictly greater than mine (keys unique -> rank is a permutation).
    int rank = 0;
    #pragma unroll
    for (int j = 0; j < MAX_DEGREE; j += 4) {
        // broadcast reads: every thread reads the same addresses -> conflict-free
        ulonglong2 a = *reinterpret_cast<const ulonglong2*>(&skey[j]);
        ulonglong2 b = *reinterpret_cast<const ulonglong2*>(&skey[j + 2]);
        rank += (a.x > mykey);
        rank += (a.y > mykey);
        rank += (b.x > mykey);
        rank += (b.y > mykey);
    }

    if (rank < NUM_SAMPLES) {
        out[(long long)row * NUM_SAMPLES + rank] = (float)nb;  // ids exact < 2^24
    }
}

extern "C" void kernel_launch(void* const* d_in, const int* in_sizes, int n_in,
                              void* d_out, int out_size)
{
    // Identify inputs by size (robust to metadata ordering). Element counts:
    //   ids: 4096, adj_info: 2,560,000, prob_matrix: 400,000,000
    const int*   ids  = nullptr;
    const int*   adj  = nullptr;
    const float* prob = nullptr;

    const long long S_IDS  = (long long)BATCH;
    const long long S_ADJ  = (long long)N_NODES * MAX_DEGREE;
    const long long S_PROB = (long long)N_NODES * N_NODES;

    for (int i = 0; i < n_in; i++) {
        long long sz = (long long)(unsigned int)in_sizes[i];
        if (sz == S_IDS  || sz == S_IDS  * 4) ids  = (const int*)d_in[i];
        else if (sz == S_ADJ  || sz == S_ADJ  * 4) adj  = (const int*)d_in[i];
        else if (sz == S_PROB || sz == S_PROB * 4) prob = (const float*)d_in[i];
    }
    if (!ids || !adj || !prob) {  // fallback: setup_inputs dict order
        ids  = (const int*)d_in[0];
        adj  = (const int*)d_in[1];
        prob = (const float*)d_in[2];
    }

    float* out = (float*)d_out;

    uns_rank_kernel<<<BATCH, THREADS>>>(ids, adj, prob, out);
}

// round 13
// speedup vs baseline: 1.4978x; 1.1379x over previous
#include <cuda_runtime.h>
#include <cuda_bf16.h>
#include <cstdint>

// UniformNeighborSampler, warp-per-row rank selection with 32-bit keys.
//
// Per row: gather 128 neighbor ids + their probs, emit top-25 ids (desc prob,
// ties -> lower index) as float32.
//
// One warp per row, 4 elements per lane. Keys are the raw float bits of w
// (w in [0,1) => positive => bit order == value order). rank = #{j: k_j > k}.
// Duplicate values (duplicate neighbors, or rare accidental float collisions)
// share a rank; detected via atomicMin(owner[rank], elem); non-owning elements
// run a rare scalar fixup rank += #{j < e: k_j == k}, exactly reproducing
// jax.lax.top_k's stable tie-break.

#define N_NODES     20000
#define MAX_DEGREE  128
#define BATCH       4096
#define NUM_SAMPLES 25
#define ROWS_PER_BLOCK 4
#define THREADS     (ROWS_PER_BLOCK * 32)

__global__ __launch_bounds__(THREADS)
void uns_rank32_kernel(const int* __restrict__ ids,
                       const int* __restrict__ adj_info,
                       const float* __restrict__ prob,
                       float* __restrict__ out)
{
    __shared__ unsigned int skey[ROWS_PER_BLOCK][MAX_DEGREE];
    __shared__ int          sown[ROWS_PER_BLOCK][MAX_DEGREE];

    const int warp = threadIdx.x >> 5;
    const int lane = threadIdx.x & 31;
    const int row  = blockIdx.x * ROWS_PER_BLOCK + warp;

    const int id = __ldg(&ids[row]);

    // coalesced: lane loads 4 consecutive neighbor ids (512B-aligned row)
    const int4 nb = reinterpret_cast<const int4*>(
                        adj_info + (long long)id * MAX_DEGREE)[lane];

    const float* prow = prob + (long long)id * N_NODES;

    // 4 independent random gathers per lane (MLP=4)
    const float w0 = __ldg(&prow[nb.x]);
    const float w1 = __ldg(&prow[nb.y]);
    const float w2 = __ldg(&prow[nb.z]);
    const float w3 = __ldg(&prow[nb.w]);

    // w in [0,1) -> positive float: raw bits are order-preserving
    const unsigned int k0 = __float_as_uint(w0);
    const unsigned int k1 = __float_as_uint(w1);
    const unsigned int k2 = __float_as_uint(w2);
    const unsigned int k3 = __float_as_uint(w3);

    reinterpret_cast<uint4*>(skey[warp])[lane] = make_uint4(k0, k1, k2, k3);
    reinterpret_cast<int4*>(sown[warp])[lane]  = make_int4(0x7FFFFFFF, 0x7FFFFFFF,
                                                           0x7FFFFFFF, 0x7FFFFFFF);
    __syncwarp();

    // rank = count of strictly-greater keys; 16 independent cmp+add per chunk
    int r0 = 0, r1 = 0, r2 = 0, r3 = 0;
    #pragma unroll 8
    for (int j = 0; j < MAX_DEGREE / 4; j++) {
        const uint4 kk = reinterpret_cast<const uint4*>(skey[warp])[j];
        r0 += (kk.x > k0); r0 += (kk.y > k0); r0 += (kk.z > k0); r0 += (kk.w > k0);
        r1 += (kk.x > k1); r1 += (kk.y > k1); r1 += (kk.z > k1); r1 += (kk.w > k1);
        r2 += (kk.x > k2); r2 += (kk.y > k2); r2 += (kk.z > k2); r2 += (kk.w > k2);
        r3 += (kk.x > k3); r3 += (kk.y > k3); r3 += (kk.z > k3); r3 += (kk.w > k3);
    }

    const int e = lane * 4;
    atomicMin(&sown[warp][r0], e + 0);
    atomicMin(&sown[warp][r1], e + 1);
    atomicMin(&sown[warp][r2], e + 2);
    atomicMin(&sown[warp][r3], e + 3);
    __syncwarp();

    float* orow = out + (long long)row * NUM_SAMPLES;

    // Per element: if I don't own my rank slot, I'm a non-minimal twin ->
    // exact stable fixup (rare: ~1-2 elements in ~half the rows).
    #pragma unroll
    for (int m = 0; m < 4; m++) {
        int           rm = (m == 0) ? r0 : (m == 1) ? r1 : (m == 2) ? r2 : r3;
        const unsigned km = (m == 0) ? k0 : (m == 1) ? k1 : (m == 2) ? k2 : k3;
        const int     nbm = (m == 0) ? nb.x : (m == 1) ? nb.y : (m == 2) ? nb.z : nb.w;
        const int      em = e + m;

        if (sown[warp][rm] != em) {
            int eq = 0;
            for (int j = 0; j < em; j++) eq += (skey[warp][j] == km);
            rm += eq;
        }
        if (rm < NUM_SAMPLES) {
            orow[rm] = (float)nbm;   // ids < 2^24: exact in float32
        }
    }
}

extern "C" void kernel_launch(void* const* d_in, const int* in_sizes, int n_in,
                              void* d_out, int out_size)
{
    // Identify inputs by size (robust to metadata ordering). Element counts:
    //   ids: 4096, adj_info: 2,560,000, prob_matrix: 400,000,000
    const int*   ids  = nullptr;
    const int*   adj  = nullptr;
    const float* prob = nullptr;

    const long long S_IDS  = (long long)BATCH;
    const long long S_ADJ  = (long long)N_NODES * MAX_DEGREE;
    const long long S_PROB = (long long)N_NODES * N_NODES;

    for (int i = 0; i < n_in; i++) {
        long long sz = (long long)(unsigned int)in_sizes[i];
        if (sz == S_IDS  || sz == S_IDS  * 4) ids  = (const int*)d_in[i];
        else if (sz == S_ADJ  || sz == S_ADJ  * 4) adj  = (const int*)d_in[i];
        else if (sz == S_PROB || sz == S_PROB * 4) prob = (const float*)d_in[i];
    }
    if (!ids || !adj || !prob) {  // fallback: setup_inputs dict order
        ids  = (const int*)d_in[0];
        adj  = (const int*)d_in[1];
        prob = (const float*)d_in[2];
    }

    float* out = (float*)d_out;

    uns_rank32_kernel<<<BATCH / ROWS_PER_BLOCK, THREADS>>>(ids, adj, prob, out);
}